// round 4
// baseline (speedup 1.0000x reference)
#include <cuda_runtime.h>
#include <math.h>
#include <stdint.h>

#define B_ 4
#define T_ 2048
#define DM_ 2048
#define H_ 16
#define KV_ 8
#define HD_ 128
#define G_ 2

// Scratch (no allocations allowed) — static device globals.
__device__ float g_q[B_*T_*H_*HD_];   // 64 MB
__device__ float g_k[B_*T_*KV_*HD_];  // 32 MB
__device__ float g_v[B_*T_*KV_*HD_];  // 32 MB
__device__ float g_o[B_*T_*H_*HD_];   // 64 MB

// ---------------------------------------------------------------------------
// TF32 / cp.async helpers
// ---------------------------------------------------------------------------
__device__ __forceinline__ uint32_t f2tf32(float f) {
    uint32_t r;
    asm("cvt.rna.tf32.f32 %0, %1;" : "=r"(r) : "f"(f));
    return r;
}

__device__ __forceinline__ void mma_tf32(float c[4],
                                         uint32_t a0, uint32_t a1, uint32_t a2, uint32_t a3,
                                         uint32_t b0, uint32_t b1) {
    asm volatile(
        "mma.sync.aligned.m16n8k8.row.col.f32.tf32.tf32.f32 "
        "{%0,%1,%2,%3}, {%4,%5,%6,%7}, {%8,%9}, {%0,%1,%2,%3};"
        : "+f"(c[0]), "+f"(c[1]), "+f"(c[2]), "+f"(c[3])
        : "r"(a0), "r"(a1), "r"(a2), "r"(a3), "r"(b0), "r"(b1));
}

__device__ __forceinline__ uint32_t smem_u32(const void* p) {
    uint32_t a;
    asm("{ .reg .u64 t; cvta.to.shared.u64 t, %1; cvt.u32.u64 %0, t; }" : "=r"(a) : "l"(p));
    return a;
}
__device__ __forceinline__ void cp16(uint32_t s, const void* g) {
    asm volatile("cp.async.ca.shared.global [%0], [%1], 16;" :: "r"(s), "l"(g));
}
#define CP_COMMIT() asm volatile("cp.async.commit_group;")
#define CP_WAIT1()  asm volatile("cp.async.wait_group 1;")

// ---------------------------------------------------------------------------
// TF32 tensor-core GEMM, cp.async double-buffered: C[M,N] = A[M,K] * W[K,N].
// Block 128x128, BK=32, 8 warps (2m x 4n), warp tile 64x32.
// smem holds raw fp32 (cp.async); cvt.rna.tf32 applied at fragment load.
// A stride 36 (==4 mod 32), B stride 136 (==8 mod 32): conflict-free frags.
// ---------------------------------------------------------------------------
#define AS_ST 36
#define BS_ST 136
#define A_SZ (128 * AS_ST)
#define B_SZ (32 * BS_ST)
#define GEMM_SMEM ((2 * (A_SZ + B_SZ)) * 4)

__global__ __launch_bounds__(256, 2)
void gemm_tf32(const float* __restrict__ A, const float* __restrict__ W,
               float* __restrict__ C, int M, int N, int K)
{
    extern __shared__ float smem[];
    float* As[2] = { smem, smem + A_SZ };
    float* Bs[2] = { smem + 2 * A_SZ, smem + 2 * A_SZ + B_SZ };

    int tid  = threadIdx.x;
    int lane = tid & 31;
    int warp = tid >> 5;
    int wm = (warp & 1) * 64;
    int wn = (warp >> 1) * 32;
    int bm = blockIdx.y * 128, bn = blockIdx.x * 128;

    // cp.async source/dest indices (16B per thread per chunk)
    int am = tid >> 3, ak = (tid & 7) << 2;       // A: 4 chunks of 32 rows
    int bk = tid >> 5, bnc = (tid & 31) << 2;     // B: 4 chunks of 8 rows

    const int NT = K / 32;
    float acc[4][4][4] = {};

    // Prefetch stage 0
    {
        uint32_t a_s = smem_u32(&As[0][am * AS_ST + ak]);
        uint32_t b_s = smem_u32(&Bs[0][bk * BS_ST + bnc]);
        #pragma unroll
        for (int p = 0; p < 4; p++) {
            cp16(a_s + p * 32 * AS_ST * 4, &A[(size_t)(bm + am + p * 32) * K + ak]);
            cp16(b_s + p * 8 * BS_ST * 4,  &W[(size_t)(bk + p * 8) * N + bn + bnc]);
        }
        CP_COMMIT();
    }

    for (int kt = 0; kt < NT; kt++) {
        int cur = kt & 1;
        // Prefetch next stage
        if (kt + 1 < NT) {
            int nxt = cur ^ 1;
            int k0 = (kt + 1) * 32;
            uint32_t a_s = smem_u32(&As[nxt][am * AS_ST + ak]);
            uint32_t b_s = smem_u32(&Bs[nxt][bk * BS_ST + bnc]);
            #pragma unroll
            for (int p = 0; p < 4; p++) {
                cp16(a_s + p * 32 * AS_ST * 4, &A[(size_t)(bm + am + p * 32) * K + k0 + ak]);
                cp16(b_s + p * 8 * BS_ST * 4,  &W[(size_t)(k0 + bk + p * 8) * N + bn + bnc]);
            }
        }
        CP_COMMIT();
        CP_WAIT1();
        __syncthreads();

        const float* a_sm = As[cur];
        const float* b_sm = Bs[cur];
        #pragma unroll
        for (int ks = 0; ks < 4; ks++) {
            int kc = ks * 8 + (lane & 3);
            uint32_t af[4][4];
            #pragma unroll
            for (int fm = 0; fm < 4; fm++) {
                int r = wm + fm * 16 + (lane >> 2);
                af[fm][0] = f2tf32(a_sm[r * AS_ST + kc]);
                af[fm][1] = f2tf32(a_sm[(r + 8) * AS_ST + kc]);
                af[fm][2] = f2tf32(a_sm[r * AS_ST + kc + 4]);
                af[fm][3] = f2tf32(a_sm[(r + 8) * AS_ST + kc + 4]);
            }
            #pragma unroll
            for (int fn = 0; fn < 4; fn++) {
                int n = wn + fn * 8 + (lane >> 2);
                uint32_t b0 = f2tf32(b_sm[kc * BS_ST + n]);
                uint32_t b1 = f2tf32(b_sm[(kc + 4) * BS_ST + n]);
                #pragma unroll
                for (int fm = 0; fm < 4; fm++)
                    mma_tf32(acc[fm][fn], af[fm][0], af[fm][1], af[fm][2], af[fm][3], b0, b1);
            }
        }
        __syncthreads();   // all reads done before this buffer is overwritten
    }

    #pragma unroll
    for (int fm = 0; fm < 4; fm++) {
        #pragma unroll
        for (int fn = 0; fn < 4; fn++) {
            int r = bm + wm + fm * 16 + (lane >> 2);
            int c = bn + wn + fn * 8 + (lane & 3) * 2;
            *(float2*)&C[(size_t)r * N + c]       = make_float2(acc[fm][fn][0], acc[fm][fn][1]);
            *(float2*)&C[(size_t)(r + 8) * N + c] = make_float2(acc[fm][fn][2], acc[fm][fn][3]);
        }
    }
}

// ---------------------------------------------------------------------------
// Fused RMSNorm + interleaved RoPE (1/sqrt(HD) folded into q). (unchanged)
// ---------------------------------------------------------------------------
__global__ void rmsrope(float* __restrict__ buf, const float* __restrict__ gamma,
                        const float* __restrict__ cosT, const float* __restrict__ sinT,
                        int nheads, float outscale)
{
    int gid  = blockIdx.x * blockDim.x + threadIdx.x;
    int lane = gid & 31;
    int w    = gid >> 5;
    int t    = (w / nheads) % T_;
    float* p = buf + (size_t)w * HD_ + lane * 4;
    float4 v = *(float4*)p;
    float ss = v.x * v.x + v.y * v.y + v.z * v.z + v.w * v.w;
    #pragma unroll
    for (int off = 16; off; off >>= 1) ss += __shfl_xor_sync(0xffffffffu, ss, off);
    float r = rsqrtf(ss * (1.0f / HD_) + 1e-6f);
    float4 g = *(const float4*)&gamma[lane * 4];
    float hx = v.x * r * g.x, hy = v.y * r * g.y;
    float hz = v.z * r * g.z, hw = v.w * r * g.w;
    int ci = t * HD_ + lane * 4;
    float c0 = cosT[ci], s0 = sinT[ci], c1 = cosT[ci + 2], s1 = sinT[ci + 2];
    float4 o;
    o.x = (hx * c0 - hy * s0) * outscale;
    o.y = (hy * c0 + hx * s0) * outscale;
    o.z = (hz * c1 - hw * s1) * outscale;
    o.w = (hw * c1 + hz * s1) * outscale;
    *(float4*)p = o;
}

// ---------------------------------------------------------------------------
// Tensor-core flash attention (non-causal). 128 q-rows/CTA, 8 warps, 64-wide
// K/V tiles, tf32 m16n8k8 for QK^T and PV. (unchanged from R2)
// ---------------------------------------------------------------------------
#define QS_ST 132
#define KS_ST 132
#define VS_ST 136
#define PS_ST 68
#define ATTN_SMEM ((128*QS_ST + 64*KS_ST + 64*VS_ST + 128*PS_ST) * 4)

__global__ __launch_bounds__(256, 1)
void attn_mma(const float* __restrict__ q, const float* __restrict__ k,
              const float* __restrict__ v, float* __restrict__ o)
{
    extern __shared__ uint32_t sm[];
    uint32_t* qs = sm;
    uint32_t* ks = qs + 128 * QS_ST;
    uint32_t* vs = ks + 64 * KS_ST;
    uint32_t* ps = vs + 64 * VS_ST;

    int b = blockIdx.z, h = blockIdx.y;
    int kvh = h / G_;
    int t0 = blockIdx.x * 128;
    int tid = threadIdx.x, lane = tid & 31, warp = tid >> 5;
    int qr = lane >> 2;
    int ql = lane & 3;

    #pragma unroll
    for (int p = 0; p < 16; p++) {
        int idx = tid + p * 256;
        int row = idx >> 5, c4 = (idx & 31) << 2;
        float4 a = *(const float4*)&q[(((size_t)(b * T_ + t0 + row) * H_ + h) << 7) + c4];
        uint32_t* d = &qs[row * QS_ST + c4];
        d[0] = f2tf32(a.x); d[1] = f2tf32(a.y); d[2] = f2tf32(a.z); d[3] = f2tf32(a.w);
    }

    float m1 = -1e30f, m2 = -1e30f, l1 = 0.f, l2 = 0.f;
    float oa[16][4] = {};
    int r1 = warp * 16 + qr;

    for (int kt = 0; kt < T_ / 64; kt++) {
        __syncthreads();
        #pragma unroll
        for (int p = 0; p < 8; p++) {
            int idx = tid + p * 256;
            int row = idx >> 5, c4 = (idx & 31) << 2;
            size_t gofs = (((size_t)(b * T_ + kt * 64 + row) * KV_ + kvh) << 7) + c4;
            float4 kk = *(const float4*)&k[gofs];
            uint32_t* dk = &ks[row * KS_ST + c4];
            dk[0] = f2tf32(kk.x); dk[1] = f2tf32(kk.y);
            dk[2] = f2tf32(kk.z); dk[3] = f2tf32(kk.w);
            float4 vv = *(const float4*)&v[gofs];
            uint32_t* dv = &vs[row * VS_ST + c4];
            dv[0] = f2tf32(vv.x); dv[1] = f2tf32(vv.y);
            dv[2] = f2tf32(vv.z); dv[3] = f2tf32(vv.w);
        }
        __syncthreads();

        float s[8][4] = {};
        #pragma unroll
        for (int kc8 = 0; kc8 < 128; kc8 += 8) {
            int kc = kc8 + ql;
            uint32_t a0 = qs[r1 * QS_ST + kc];
            uint32_t a1 = qs[(r1 + 8) * QS_ST + kc];
            uint32_t a2 = qs[r1 * QS_ST + kc + 4];
            uint32_t a3 = qs[(r1 + 8) * QS_ST + kc + 4];
            #pragma unroll
            for (int nf = 0; nf < 8; nf++) {
                int n = nf * 8 + qr;
                uint32_t b0 = ks[n * KS_ST + kc];
                uint32_t b1 = ks[n * KS_ST + kc + 4];
                mma_tf32(s[nf], a0, a1, a2, a3, b0, b1);
            }
        }

        float rm1 = -1e30f, rm2 = -1e30f;
        #pragma unroll
        for (int nf = 0; nf < 8; nf++) {
            rm1 = fmaxf(rm1, fmaxf(s[nf][0], s[nf][1]));
            rm2 = fmaxf(rm2, fmaxf(s[nf][2], s[nf][3]));
        }
        #pragma unroll
        for (int off = 1; off <= 2; off <<= 1) {
            rm1 = fmaxf(rm1, __shfl_xor_sync(0xffffffffu, rm1, off));
            rm2 = fmaxf(rm2, __shfl_xor_sync(0xffffffffu, rm2, off));
        }
        float nm1 = fmaxf(m1, rm1), nm2 = fmaxf(m2, rm2);
        float rs1 = 0.f, rs2 = 0.f;
        #pragma unroll
        for (int nf = 0; nf < 8; nf++) {
            float p0 = __expf(s[nf][0] - nm1);
            float p1 = __expf(s[nf][1] - nm1);
            float p2 = __expf(s[nf][2] - nm2);
            float p3 = __expf(s[nf][3] - nm2);
            rs1 += p0 + p1; rs2 += p2 + p3;
            int c = nf * 8 + ql * 2;
            ps[r1 * PS_ST + c]           = f2tf32(p0);
            ps[r1 * PS_ST + c + 1]       = f2tf32(p1);
            ps[(r1 + 8) * PS_ST + c]     = f2tf32(p2);
            ps[(r1 + 8) * PS_ST + c + 1] = f2tf32(p3);
        }
        #pragma unroll
        for (int off = 1; off <= 2; off <<= 1) {
            rs1 += __shfl_xor_sync(0xffffffffu, rs1, off);
            rs2 += __shfl_xor_sync(0xffffffffu, rs2, off);
        }
        float corr1 = __expf(m1 - nm1), corr2 = __expf(m2 - nm2);
        l1 = l1 * corr1 + rs1; m1 = nm1;
        l2 = l2 * corr2 + rs2; m2 = nm2;
        #pragma unroll
        for (int nf = 0; nf < 16; nf++) {
            oa[nf][0] *= corr1; oa[nf][1] *= corr1;
            oa[nf][2] *= corr2; oa[nf][3] *= corr2;
        }
        __syncwarp();

        #pragma unroll
        for (int kc8 = 0; kc8 < 64; kc8 += 8) {
            int kc = kc8 + ql;
            uint32_t a0 = ps[r1 * PS_ST + kc];
            uint32_t a1 = ps[(r1 + 8) * PS_ST + kc];
            uint32_t a2 = ps[r1 * PS_ST + kc + 4];
            uint32_t a3 = ps[(r1 + 8) * PS_ST + kc + 4];
            #pragma unroll
            for (int nf = 0; nf < 16; nf++) {
                int n = nf * 8 + qr;
                uint32_t b0 = vs[kc * VS_ST + n];
                uint32_t b1 = vs[(kc + 4) * VS_ST + n];
                mma_tf32(oa[nf], a0, a1, a2, a3, b0, b1);
            }
        }
    }

    float inv1 = 1.0f / l1, inv2 = 1.0f / l2;
    size_t base1 = ((size_t)(b * T_ + t0 + r1) * H_ + h) << 7;
    size_t base2 = ((size_t)(b * T_ + t0 + r1 + 8) * H_ + h) << 7;
    #pragma unroll
    for (int nf = 0; nf < 16; nf++) {
        int c = nf * 8 + ql * 2;
        *(float2*)&o[base1 + c] = make_float2(oa[nf][0] * inv1, oa[nf][1] * inv1);
        *(float2*)&o[base2 + c] = make_float2(oa[nf][2] * inv2, oa[nf][3] * inv2);
    }
}

// ---------------------------------------------------------------------------
// Launch
// ---------------------------------------------------------------------------
extern "C" void kernel_launch(void* const* d_in, const int* in_sizes, int n_in,
                              void* d_out, int out_size)
{
    const float* x    = (const float*)d_in[0];
    const float* cosT = (const float*)d_in[1];
    const float* sinT = (const float*)d_in[2];
    const float* Wq   = (const float*)d_in[3];
    const float* Wk   = (const float*)d_in[4];
    const float* Wv   = (const float*)d_in[5];
    const float* Wo   = (const float*)d_in[6];
    const float* qg   = (const float*)d_in[7];
    const float* kg   = (const float*)d_in[8];

    float *q, *k, *v, *o;
    cudaGetSymbolAddress((void**)&q, g_q);
    cudaGetSymbolAddress((void**)&k, g_k);
    cudaGetSymbolAddress((void**)&v, g_v);
    cudaGetSymbolAddress((void**)&o, g_o);

    const int M = B_ * T_;  // 8192

    cudaFuncSetAttribute(gemm_tf32, cudaFuncAttributeMaxDynamicSharedMemorySize, GEMM_SMEM);
    gemm_tf32<<<dim3((H_ * HD_) / 128, M / 128), 256, GEMM_SMEM>>>(x, Wq, q, M, H_ * HD_, DM_);
    gemm_tf32<<<dim3((KV_ * HD_) / 128, M / 128), 256, GEMM_SMEM>>>(x, Wk, k, M, KV_ * HD_, DM_);
    gemm_tf32<<<dim3((KV_ * HD_) / 128, M / 128), 256, GEMM_SMEM>>>(x, Wv, v, M, KV_ * HD_, DM_);

    rmsrope<<<(M * H_) / 8, 256>>>(q, qg, cosT, sinT, H_, 0.0883883476483184405f);
    rmsrope<<<(M * KV_) / 8, 256>>>(k, kg, cosT, sinT, KV_, 1.0f);

    cudaFuncSetAttribute(attn_mma, cudaFuncAttributeMaxDynamicSharedMemorySize, ATTN_SMEM);
    attn_mma<<<dim3(T_ / 128, H_, B_), 256, ATTN_SMEM>>>(q, k, v, o);

    gemm_tf32<<<dim3(DM_ / 128, M / 128), 256, GEMM_SMEM>>>(o, Wo, (float*)d_out, M, DM_, DM_);
}

// round 6
// speedup vs baseline: 1.5780x; 1.5780x over previous
#include <cuda_runtime.h>
#include <cuda_fp16.h>
#include <math.h>
#include <stdint.h>

#define B_ 4
#define T_ 2048
#define DM_ 2048
#define H_ 16
#define KV_ 8
#define HD_ 128
#define G_ 2

// Scratch (no allocations allowed) — static device globals.
__device__ float  g_q[B_*T_*H_*HD_];    // 64 MB
__device__ float  g_k[B_*T_*KV_*HD_];   // 32 MB
__device__ float  g_v[B_*T_*KV_*HD_];   // 32 MB
__device__ float  g_o[B_*T_*H_*HD_];    // 64 MB
__device__ __half g_wt[12*1024*1024];   // 24 MB: WqT(4M) WkT(2M) WvT(2M) WoT(4M) halfs

// ---------------------------------------------------------------------------
// Helpers
// ---------------------------------------------------------------------------
__device__ __forceinline__ uint32_t h2u(__half2 h) { return *(uint32_t*)&h; }
__device__ __forceinline__ uint32_t pack2(float lo, float hi) {
    return h2u(__floats2half2_rn(lo, hi));
}

__device__ __forceinline__ void mma_f16(float c[4],
                                        uint32_t a0, uint32_t a1, uint32_t a2, uint32_t a3,
                                        uint32_t b0, uint32_t b1) {
    asm volatile(
        "mma.sync.aligned.m16n8k16.row.col.f32.f16.f16.f32 "
        "{%0,%1,%2,%3}, {%4,%5,%6,%7}, {%8,%9}, {%0,%1,%2,%3};"
        : "+f"(c[0]), "+f"(c[1]), "+f"(c[2]), "+f"(c[3])
        : "r"(a0), "r"(a1), "r"(a2), "r"(a3), "r"(b0), "r"(b1));
}

// ---------------------------------------------------------------------------
// Weight transpose + fp16 convert: W[K][N] -> WT[N][K] (half).
// ---------------------------------------------------------------------------
__global__ void transpose_cvt(const float* __restrict__ W, __half* __restrict__ WT,
                              int K, int N)
{
    __shared__ float t[32][33];
    int n0 = blockIdx.x * 32, k0 = blockIdx.y * 32;
    int tx = threadIdx.x & 31, ty = threadIdx.x >> 5;
    #pragma unroll
    for (int j = 0; j < 4; j++)
        t[ty + 8 * j][tx] = W[(size_t)(k0 + ty + 8 * j) * N + n0 + tx];
    __syncthreads();
    #pragma unroll
    for (int j = 0; j < 4; j++)
        WT[(size_t)(n0 + ty + 8 * j) * K + k0 + tx] = __float2half_rn(t[tx][ty + 8 * j]);
}

// ---------------------------------------------------------------------------
// FP16 tensor-core GEMM: C[M,N] = A[M,K] * WT[N,K]^T.
// Block 128x128, BK=32, 8 warps (2m x 4n), warp tile 64x32, m16n8k16.
// Smem rows stride 40 halfs (ST/2 = 20 ≡ 4 mod 32): fragment half2 loads hit
// 32 distinct banks across the warp.
// ---------------------------------------------------------------------------
#define GA_ST 40

__global__ __launch_bounds__(256, 2)
void gemm_f16(const float* __restrict__ A, const __half* __restrict__ WT,
              float* __restrict__ C, int M, int N, int K)
{
    __shared__ __half As[128 * GA_ST];
    __shared__ __half Bs[128 * GA_ST];

    int tid  = threadIdx.x;
    int lane = tid & 31;
    int warp = tid >> 5;
    int qr = lane >> 2, ql = lane & 3;
    int wm = (warp & 1) * 64;
    int wn = (warp >> 1) * 32;
    int bm = blockIdx.y * 128, bn = blockIdx.x * 128;

    float acc[4][4][4] = {};

    for (int k0 = 0; k0 < K; k0 += 32) {
        // Stage A 128x32: fp32 -> half
        #pragma unroll
        for (int p = 0; p < 4; p++) {
            int slot = p * 256 + tid;
            int m = slot >> 3, k4 = (slot & 7) << 2;
            float4 a = *(const float4*)&A[(size_t)(bm + m) * K + k0 + k4];
            uint2 u = make_uint2(pack2(a.x, a.y), pack2(a.z, a.w));
            *(uint2*)&As[m * GA_ST + k4] = u;
        }
        // Stage B 128n x 32k from pre-halved WT
        #pragma unroll
        for (int p = 0; p < 4; p++) {
            int slot = p * 256 + tid;
            int n = slot >> 3, k4 = (slot & 7) << 2;
            *(uint2*)&Bs[n * GA_ST + k4] = *(const uint2*)&WT[(size_t)(bn + n) * K + k0 + k4];
        }
        __syncthreads();

        #pragma unroll
        for (int ks = 0; ks < 2; ks++) {
            int kc = ks * 16 + ql * 2;
            uint32_t af[4][4];
            #pragma unroll
            for (int fm = 0; fm < 4; fm++) {
                int r = wm + fm * 16 + qr;
                af[fm][0] = *(const uint32_t*)&As[r * GA_ST + kc];
                af[fm][1] = *(const uint32_t*)&As[(r + 8) * GA_ST + kc];
                af[fm][2] = *(const uint32_t*)&As[r * GA_ST + kc + 8];
                af[fm][3] = *(const uint32_t*)&As[(r + 8) * GA_ST + kc + 8];
            }
            #pragma unroll
            for (int fn = 0; fn < 4; fn++) {
                int n = wn + fn * 8 + qr;
                uint32_t b0 = *(const uint32_t*)&Bs[n * GA_ST + kc];
                uint32_t b1 = *(const uint32_t*)&Bs[n * GA_ST + kc + 8];
                #pragma unroll
                for (int fm = 0; fm < 4; fm++)
                    mma_f16(acc[fm][fn], af[fm][0], af[fm][1], af[fm][2], af[fm][3], b0, b1);
            }
        }
        __syncthreads();
    }

    #pragma unroll
    for (int fm = 0; fm < 4; fm++) {
        #pragma unroll
        for (int fn = 0; fn < 4; fn++) {
            int r = bm + wm + fm * 16 + qr;
            int c = bn + wn + fn * 8 + ql * 2;
            *(float2*)&C[(size_t)r * N + c]       = make_float2(acc[fm][fn][0], acc[fm][fn][1]);
            *(float2*)&C[(size_t)(r + 8) * N + c] = make_float2(acc[fm][fn][2], acc[fm][fn][3]);
        }
    }
}

// ---------------------------------------------------------------------------
// Fused RMSNorm + interleaved RoPE (1/sqrt(HD) folded into q). (unchanged)
// ---------------------------------------------------------------------------
__global__ void rmsrope(float* __restrict__ buf, const float* __restrict__ gamma,
                        const float* __restrict__ cosT, const float* __restrict__ sinT,
                        int nheads, float outscale)
{
    int gid  = blockIdx.x * blockDim.x + threadIdx.x;
    int lane = gid & 31;
    int w    = gid >> 5;
    int t    = (w / nheads) % T_;
    float* p = buf + (size_t)w * HD_ + lane * 4;
    float4 v = *(float4*)p;
    float ss = v.x * v.x + v.y * v.y + v.z * v.z + v.w * v.w;
    #pragma unroll
    for (int off = 16; off; off >>= 1) ss += __shfl_xor_sync(0xffffffffu, ss, off);
    float r = rsqrtf(ss * (1.0f / HD_) + 1e-6f);
    float4 g = *(const float4*)&gamma[lane * 4];
    float hx = v.x * r * g.x, hy = v.y * r * g.y;
    float hz = v.z * r * g.z, hw = v.w * r * g.w;
    int ci = t * HD_ + lane * 4;
    float c0 = cosT[ci], s0 = sinT[ci], c1 = cosT[ci + 2], s1 = sinT[ci + 2];
    float4 o;
    o.x = (hx * c0 - hy * s0) * outscale;
    o.y = (hy * c0 + hx * s0) * outscale;
    o.z = (hz * c1 - hw * s1) * outscale;
    o.w = (hw * c1 + hz * s1) * outscale;
    *(float4*)p = o;
}

// ---------------------------------------------------------------------------
// FP16 tensor-core flash attention. 128 q-rows/CTA, 8 warps (16 rows each),
// 64-wide K/V tiles, m16n8k16 for QK^T and PV.
//   qs,ks: [row][hd] stride 136 halfs (68 ≡ 4 mod 32 -> conflict-free frags)
//   vs:    V transposed [hd][s] stride 72 (36 ≡ 4 mod 32)
//   ps:    [row][s] stride 72
// ---------------------------------------------------------------------------
#define AQ_ST 136
#define AV_ST 72
#define AP_ST 72
#define ATTN_SMEM ((128*AQ_ST + 64*AQ_ST + 128*AV_ST + 128*AP_ST) * 2)

__global__ __launch_bounds__(256, 1)
void attn_f16(const float* __restrict__ q, const float* __restrict__ k,
              const float* __restrict__ v, float* __restrict__ o)
{
    extern __shared__ __half hsm[];
    __half* qs = hsm;                     // 128 x 136
    __half* ks = qs + 128 * AQ_ST;        // 64 x 136
    __half* vs = ks + 64 * AQ_ST;         // 128(hd) x 72(s)
    __half* ps = vs + 128 * AV_ST;        // 128 x 72

    int b = blockIdx.z, h = blockIdx.y;
    int kvh = h / G_;
    int t0 = blockIdx.x * 128;
    int tid = threadIdx.x, lane = tid & 31, warp = tid >> 5;
    int qr = lane >> 2;
    int ql = lane & 3;

    // Stage Q tile (128 x 128) once as half.
    #pragma unroll
    for (int p = 0; p < 16; p++) {
        int slot = p * 256 + tid;
        int row = slot >> 5, c4 = (slot & 31) << 2;
        float4 a = *(const float4*)&q[(((size_t)(b * T_ + t0 + row) * H_ + h) << 7) + c4];
        *(uint2*)&qs[row * AQ_ST + c4] = make_uint2(pack2(a.x, a.y), pack2(a.z, a.w));
    }

    float m1 = -1e30f, m2 = -1e30f, l1 = 0.f, l2 = 0.f;
    float oa[16][4] = {};
    int r1 = warp * 16 + qr;

    for (int kt = 0; kt < T_ / 64; kt++) {
        __syncthreads();
        // Stage K (64 x 128) as half, row-major.
        #pragma unroll
        for (int p = 0; p < 8; p++) {
            int slot = p * 256 + tid;
            int row = slot >> 5, c4 = (slot & 31) << 2;
            size_t gofs = (((size_t)(b * T_ + kt * 64 + row) * KV_ + kvh) << 7) + c4;
            float4 kk = *(const float4*)&k[gofs];
            *(uint2*)&ks[row * AQ_ST + c4] = make_uint2(pack2(kk.x, kk.y), pack2(kk.z, kk.w));
        }
        // Stage V transposed: vs[hd][s].  Thread covers (hd, s4-group of 4 s).
        #pragma unroll
        for (int p = 0; p < 8; p++) {
            int slot = p * 256 + tid;
            int hd = slot & 127, s0 = (slot >> 7) << 2;
            size_t gbase = (((size_t)(b * T_ + kt * 64 + s0) * KV_ + kvh) << 7) + hd;
            const size_t stp = (size_t)KV_ << 7;
            float v0 = v[gbase], v1 = v[gbase + stp], v2 = v[gbase + 2 * stp], v3 = v[gbase + 3 * stp];
            *(uint2*)&vs[hd * AV_ST + s0] = make_uint2(pack2(v0, v1), pack2(v2, v3));
        }
        __syncthreads();

        // S = Q @ K^T : 8 k16 steps over HD=128, 8 n-frags over 64 cols.
        float s[8][4] = {};
        #pragma unroll
        for (int k16 = 0; k16 < 128; k16 += 16) {
            int kc = k16 + ql * 2;
            uint32_t a0 = *(const uint32_t*)&qs[r1 * AQ_ST + kc];
            uint32_t a1 = *(const uint32_t*)&qs[(r1 + 8) * AQ_ST + kc];
            uint32_t a2 = *(const uint32_t*)&qs[r1 * AQ_ST + kc + 8];
            uint32_t a3 = *(const uint32_t*)&qs[(r1 + 8) * AQ_ST + kc + 8];
            #pragma unroll
            for (int nf = 0; nf < 8; nf++) {
                int n = nf * 8 + qr;
                uint32_t b0 = *(const uint32_t*)&ks[n * AQ_ST + kc];
                uint32_t b1 = *(const uint32_t*)&ks[n * AQ_ST + kc + 8];
                mma_f16(s[nf], a0, a1, a2, a3, b0, b1);
            }
        }

        // Online softmax (rows r1, r1+8; groups of 4 lanes share a row).
        float rm1 = -1e30f, rm2 = -1e30f;
        #pragma unroll
        for (int nf = 0; nf < 8; nf++) {
            rm1 = fmaxf(rm1, fmaxf(s[nf][0], s[nf][1]));
            rm2 = fmaxf(rm2, fmaxf(s[nf][2], s[nf][3]));
        }
        #pragma unroll
        for (int off = 1; off <= 2; off <<= 1) {
            rm1 = fmaxf(rm1, __shfl_xor_sync(0xffffffffu, rm1, off));
            rm2 = fmaxf(rm2, __shfl_xor_sync(0xffffffffu, rm2, off));
        }
        float nm1 = fmaxf(m1, rm1), nm2 = fmaxf(m2, rm2);
        float rs1 = 0.f, rs2 = 0.f;
        #pragma unroll
        for (int nf = 0; nf < 8; nf++) {
            float p0 = __expf(s[nf][0] - nm1);
            float p1 = __expf(s[nf][1] - nm1);
            float p2 = __expf(s[nf][2] - nm2);
            float p3 = __expf(s[nf][3] - nm2);
            rs1 += p0 + p1; rs2 += p2 + p3;
            int c = nf * 8 + ql * 2;
            *(uint32_t*)&ps[r1 * AP_ST + c]       = pack2(p0, p1);
            *(uint32_t*)&ps[(r1 + 8) * AP_ST + c] = pack2(p2, p3);
        }
        #pragma unroll
        for (int off = 1; off <= 2; off <<= 1) {
            rs1 += __shfl_xor_sync(0xffffffffu, rs1, off);
            rs2 += __shfl_xor_sync(0xffffffffu, rs2, off);
        }
        float corr1 = __expf(m1 - nm1), corr2 = __expf(m2 - nm2);
        l1 = l1 * corr1 + rs1; m1 = nm1;
        l2 = l2 * corr2 + rs2; m2 = nm2;
        #pragma unroll
        for (int nf = 0; nf < 16; nf++) {
            oa[nf][0] *= corr1; oa[nf][1] *= corr1;
            oa[nf][2] *= corr2; oa[nf][3] *= corr2;
        }
        __syncwarp();  // P stripe is warp-private

        // O += P @ V : 4 k16 steps over s=64, 16 n-frags over hd=128.
        #pragma unroll
        for (int k16 = 0; k16 < 64; k16 += 16) {
            int kc = k16 + ql * 2;
            uint32_t a0 = *(const uint32_t*)&ps[r1 * AP_ST + kc];
            uint32_t a1 = *(const uint32_t*)&ps[(r1 + 8) * AP_ST + kc];
            uint32_t a2 = *(const uint32_t*)&ps[r1 * AP_ST + kc + 8];
            uint32_t a3 = *(const uint32_t*)&ps[(r1 + 8) * AP_ST + kc + 8];
            #pragma unroll
            for (int nf = 0; nf < 16; nf++) {
                int n = nf * 8 + qr;
                uint32_t b0 = *(const uint32_t*)&vs[n * AV_ST + kc];
                uint32_t b1 = *(const uint32_t*)&vs[n * AV_ST + kc + 8];
                mma_f16(oa[nf], a0, a1, a2, a3, b0, b1);
            }
        }
    }

    float inv1 = 1.0f / l1, inv2 = 1.0f / l2;
    size_t base1 = ((size_t)(b * T_ + t0 + r1) * H_ + h) << 7;
    size_t base2 = ((size_t)(b * T_ + t0 + r1 + 8) * H_ + h) << 7;
    #pragma unroll
    for (int nf = 0; nf < 16; nf++) {
        int c = nf * 8 + ql * 2;
        *(float2*)&o[base1 + c] = make_float2(oa[nf][0] * inv1, oa[nf][1] * inv1);
        *(float2*)&o[base2 + c] = make_float2(oa[nf][2] * inv2, oa[nf][3] * inv2);
    }
}

// ---------------------------------------------------------------------------
// Launch: transpose weights (fp16) -> GEMMs -> rmsrope -> attn -> Wo GEMM
// ---------------------------------------------------------------------------
extern "C" void kernel_launch(void* const* d_in, const int* in_sizes, int n_in,
                              void* d_out, int out_size)
{
    const float* x    = (const float*)d_in[0];
    const float* cosT = (const float*)d_in[1];
    const float* sinT = (const float*)d_in[2];
    const float* Wq   = (const float*)d_in[3];
    const float* Wk   = (const float*)d_in[4];
    const float* Wv   = (const float*)d_in[5];
    const float* Wo   = (const float*)d_in[6];
    const float* qg   = (const float*)d_in[7];
    const float* kg   = (const float*)d_in[8];

    float *q, *k, *v, *o;
    __half* wt;
    cudaGetSymbolAddress((void**)&q, g_q);
    cudaGetSymbolAddress((void**)&k, g_k);
    cudaGetSymbolAddress((void**)&v, g_v);
    cudaGetSymbolAddress((void**)&o, g_o);
    cudaGetSymbolAddress((void**)&wt, g_wt);

    __half* WqT = wt;                       // [2048][2048]
    __half* WkT = wt + 4 * 1024 * 1024;     // [1024][2048]
    __half* WvT = wt + 6 * 1024 * 1024;     // [1024][2048]
    __half* WoT = wt + 8 * 1024 * 1024;     // [2048][2048]

    const int M = B_ * T_;  // 8192

    transpose_cvt<<<dim3(2048/32, 2048/32), 256>>>(Wq, WqT, DM_, 2048);
    transpose_cvt<<<dim3(1024/32, 2048/32), 256>>>(Wk, WkT, DM_, 1024);
    transpose_cvt<<<dim3(1024/32, 2048/32), 256>>>(Wv, WvT, DM_, 1024);
    transpose_cvt<<<dim3(2048/32, 2048/32), 256>>>(Wo, WoT, H_*HD_, 2048);

    gemm_f16<<<dim3((H_*HD_)/128, M/128), 256>>>(x, WqT, q, M, H_*HD_, DM_);
    gemm_f16<<<dim3((KV_*HD_)/128, M/128), 256>>>(x, WkT, k, M, KV_*HD_, DM_);
    gemm_f16<<<dim3((KV_*HD_)/128, M/128), 256>>>(x, WvT, v, M, KV_*HD_, DM_);

    rmsrope<<<(M * H_) / 8, 256>>>(q, qg, cosT, sinT, H_, 0.0883883476483184405f);
    rmsrope<<<(M * KV_) / 8, 256>>>(k, kg, cosT, sinT, KV_, 1.0f);

    cudaFuncSetAttribute(attn_f16, cudaFuncAttributeMaxDynamicSharedMemorySize, ATTN_SMEM);
    attn_f16<<<dim3(T_ / 128, H_, B_), 256, ATTN_SMEM>>>(q, k, v, o);

    gemm_f16<<<dim3(DM_/128, M/128), 256>>>(o, WoT, (float*)d_out, M, DM_, DM_);
}

// round 7
// speedup vs baseline: 2.1973x; 1.3924x over previous
#include <cuda_runtime.h>
#include <cuda_fp16.h>
#include <math.h>
#include <stdint.h>

#define B_ 4
#define T_ 2048
#define DM_ 2048
#define H_ 16
#define KV_ 8
#define HD_ 128
#define G_ 2

// Scratch (no allocations allowed) — static device globals.
__device__ float  g_q[B_*T_*H_*HD_];    // 64 MB fp32 (QKV GEMM out, rmsrope in)
__device__ float  g_k[B_*T_*KV_*HD_];   // 32 MB
__device__ float  g_v[B_*T_*KV_*HD_];   // 32 MB
__device__ __half g_xh[B_*T_*DM_];      // 32 MB
__device__ __half g_qh[B_*T_*H_*HD_];   // 32 MB
__device__ __half g_kh[B_*T_*KV_*HD_];  // 16 MB
__device__ __half g_vt[B_*KV_*HD_*T_];  // 16 MB  V transposed [b][kv][hd][t]
__device__ __half g_oh[B_*T_*H_*HD_];   // 32 MB
__device__ __half g_wt[12*1024*1024];   // 24 MB: WqkvT [4096][2048], WoT [2048][2048]

// ---------------------------------------------------------------------------
// Helpers
// ---------------------------------------------------------------------------
__device__ __forceinline__ uint32_t h2u(__half2 h) { return *(uint32_t*)&h; }
__device__ __forceinline__ uint32_t pack2(float lo, float hi) {
    return h2u(__floats2half2_rn(lo, hi));
}

__device__ __forceinline__ void mma_f16(float c[4],
                                        uint32_t a0, uint32_t a1, uint32_t a2, uint32_t a3,
                                        uint32_t b0, uint32_t b1) {
    asm volatile(
        "mma.sync.aligned.m16n8k16.row.col.f32.f16.f16.f32 "
        "{%0,%1,%2,%3}, {%4,%5,%6,%7}, {%8,%9}, {%0,%1,%2,%3};"
        : "+f"(c[0]), "+f"(c[1]), "+f"(c[2]), "+f"(c[3])
        : "r"(a0), "r"(a1), "r"(a2), "r"(a3), "r"(b0), "r"(b1));
}

__device__ __forceinline__ uint32_t smem_u32(const void* p) {
    uint32_t a;
    asm("{ .reg .u64 t; cvta.to.shared.u64 t, %1; cvt.u32.u64 %0, t; }" : "=r"(a) : "l"(p));
    return a;
}
__device__ __forceinline__ void cp16(uint32_t s, const void* g) {
    asm volatile("cp.async.ca.shared.global [%0], [%1], 16;" :: "r"(s), "l"(g));
}
#define CP_COMMIT() asm volatile("cp.async.commit_group;")
#define CP_WAIT1()  asm volatile("cp.async.wait_group 1;")

// ---------------------------------------------------------------------------
// Weight transpose + fp16 convert: W[K][N] -> WT[N][K] (half).
// ---------------------------------------------------------------------------
__global__ void transpose_cvt(const float* __restrict__ W, __half* __restrict__ WT,
                              int K, int N)
{
    __shared__ float t[32][33];
    int n0 = blockIdx.x * 32, k0 = blockIdx.y * 32;
    int tx = threadIdx.x & 31, ty = threadIdx.x >> 5;
    #pragma unroll
    for (int j = 0; j < 4; j++)
        t[ty + 8 * j][tx] = W[(size_t)(k0 + ty + 8 * j) * N + n0 + tx];
    __syncthreads();
    #pragma unroll
    for (int j = 0; j < 4; j++)
        WT[(size_t)(n0 + ty + 8 * j) * K + k0 + tx] = __float2half_rn(t[tx][ty + 8 * j]);
}

// fp32 -> fp16 bulk convert (8 elements/thread).
__global__ void cvt_half(const float* __restrict__ in, __half* __restrict__ out)
{
    size_t i = ((size_t)blockIdx.x * blockDim.x + threadIdx.x) * 8;
    float4 a = *(const float4*)&in[i];
    float4 b = *(const float4*)&in[i + 4];
    *(uint4*)&out[i] = make_uint4(pack2(a.x, a.y), pack2(a.z, a.w),
                                  pack2(b.x, b.y), pack2(b.z, b.w));
}

// V transpose: v[b][t][kv][hd] fp32 -> vt[b][kv][hd][t] fp16.
__global__ void vtrans(const float* __restrict__ v, __half* __restrict__ vt)
{
    __shared__ float t[32][33];
    int t0 = blockIdx.x * 32, d0 = blockIdx.y * 32;
    int bk = blockIdx.z;                       // b*KV + kvh
    int b = bk >> 3, kvh = bk & 7;
    int tx = threadIdx.x & 31, ty = threadIdx.x >> 5;
    #pragma unroll
    for (int j = 0; j < 4; j++)
        t[ty + 8 * j][tx] = v[(((size_t)(b * T_ + t0 + ty + 8 * j) * KV_ + kvh) << 7) + d0 + tx];
    __syncthreads();
    #pragma unroll
    for (int j = 0; j < 4; j++)
        vt[((size_t)bk * HD_ + d0 + ty + 8 * j) * T_ + t0 + tx] = __float2half_rn(t[tx][ty + 8 * j]);
}

// ---------------------------------------------------------------------------
// All-fp16 pipelined GEMM: C[M,N] = A[M,K] * WT[N,K]^T, C fp32.
// Block 128x128, BK=64, cp.async 2-stage, 8 warps (2m x 4n), m16n8k16.
// Smem row stride 72 halfs (36 words ≡ 4 mod 32): conflict-free u32 frags.
// Fused-QKV routing: when Ck != null, cols [0,2048)->Cq ld2048,
// [2048,3072)->Ck ld1024, [3072,4096)->Cv ld1024.
// ---------------------------------------------------------------------------
#define GST 72
#define GT_SZ (128 * GST)                    // halfs per tile buffer
#define GEMM_SMEM (4 * GT_SZ * 2)            // A0 A1 B0 B1, bytes = 73728

__global__ __launch_bounds__(256, 2)
void gemm_f16h(const __half* __restrict__ A, const __half* __restrict__ WT,
               float* __restrict__ Cq, float* __restrict__ Ck, float* __restrict__ Cv,
               int M, int N, int K)
{
    extern __shared__ __half gsm[];
    __half* As[2] = { gsm, gsm + GT_SZ };
    __half* Bs[2] = { gsm + 2 * GT_SZ, gsm + 3 * GT_SZ };

    int tid  = threadIdx.x;
    int lane = tid & 31;
    int warp = tid >> 5;
    int qr = lane >> 2, ql = lane & 3;
    int wm = (warp & 1) * 64;
    int wn = (warp >> 1) * 32;
    int bm = blockIdx.y * 128, bn = blockIdx.x * 128;

    // cp.async indices: 16B = 8 halfs; 128 rows x 8 chunks = 1024 / 256 = 4 per thread
    int crow = tid >> 1, cc = (tid & 1) << 3;   // rows 0..127, col chunk 0/8 then +16/+24... 
    // simpler: slot-based below.

    float acc[4][4][4] = {};
    const int NT = K / 64;

    // Prefetch tile 0
    #pragma unroll
    for (int p = 0; p < 4; p++) {
        int slot = p * 256 + tid;
        int r = slot >> 3, c8 = (slot & 7) << 3;
        cp16(smem_u32(&As[0][r * GST + c8]), &A[(size_t)(bm + r) * K + c8]);
        cp16(smem_u32(&Bs[0][r * GST + c8]), &WT[(size_t)(bn + r) * K + c8]);
    }
    CP_COMMIT();

    for (int kt = 0; kt < NT; kt++) {
        int buf = kt & 1;
        if (kt + 1 < NT) {
            int nxt = buf ^ 1;
            int k0 = (kt + 1) * 64;
            #pragma unroll
            for (int p = 0; p < 4; p++) {
                int slot = p * 256 + tid;
                int r = slot >> 3, c8 = (slot & 7) << 3;
                cp16(smem_u32(&As[nxt][r * GST + c8]), &A[(size_t)(bm + r) * K + k0 + c8]);
                cp16(smem_u32(&Bs[nxt][r * GST + c8]), &WT[(size_t)(bn + r) * K + k0 + c8]);
            }
        }
        CP_COMMIT();
        CP_WAIT1();
        __syncthreads();

        const __half* a_sm = As[buf];
        const __half* b_sm = Bs[buf];
        #pragma unroll
        for (int ks = 0; ks < 4; ks++) {
            int kc = ks * 16 + ql * 2;
            uint32_t af[4][4];
            #pragma unroll
            for (int fm = 0; fm < 4; fm++) {
                int r = wm + fm * 16 + qr;
                af[fm][0] = *(const uint32_t*)&a_sm[r * GST + kc];
                af[fm][1] = *(const uint32_t*)&a_sm[(r + 8) * GST + kc];
                af[fm][2] = *(const uint32_t*)&a_sm[r * GST + kc + 8];
                af[fm][3] = *(const uint32_t*)&a_sm[(r + 8) * GST + kc + 8];
            }
            #pragma unroll
            for (int fn = 0; fn < 4; fn++) {
                int n = wn + fn * 8 + qr;
                uint32_t b0 = *(const uint32_t*)&b_sm[n * GST + kc];
                uint32_t b1 = *(const uint32_t*)&b_sm[n * GST + kc + 8];
                #pragma unroll
                for (int fm = 0; fm < 4; fm++)
                    mma_f16(acc[fm][fn], af[fm][0], af[fm][1], af[fm][2], af[fm][3], b0, b1);
            }
        }
        __syncthreads();
    }

    // Epilogue routing
    float* Cb; int ldc, cofs;
    if (Ck == nullptr)      { Cb = Cq; ldc = N;    cofs = bn; }
    else if (bn < 2048)     { Cb = Cq; ldc = 2048; cofs = bn; }
    else if (bn < 3072)     { Cb = Ck; ldc = 1024; cofs = bn - 2048; }
    else                    { Cb = Cv; ldc = 1024; cofs = bn - 3072; }

    #pragma unroll
    for (int fm = 0; fm < 4; fm++) {
        #pragma unroll
        for (int fn = 0; fn < 4; fn++) {
            int r = bm + wm + fm * 16 + qr;
            int c = cofs + wn + fn * 8 + ql * 2;
            *(float2*)&Cb[(size_t)r * ldc + c]       = make_float2(acc[fm][fn][0], acc[fm][fn][1]);
            *(float2*)&Cb[(size_t)(r + 8) * ldc + c] = make_float2(acc[fm][fn][2], acc[fm][fn][3]);
        }
    }
}

// ---------------------------------------------------------------------------
// Fused RMSNorm + interleaved RoPE; fp32 in, fp16 out (1/sqrt(HD) folded into q).
// ---------------------------------------------------------------------------
__global__ void rmsrope_h(const float* __restrict__ in, __half* __restrict__ outh,
                          const float* __restrict__ gamma,
                          const float* __restrict__ cosT, const float* __restrict__ sinT,
                          int nheads, float outscale)
{
    int gid  = blockIdx.x * blockDim.x + threadIdx.x;
    int lane = gid & 31;
    int w    = gid >> 5;
    int t    = (w / nheads) % T_;
    const float* p = in + (size_t)w * HD_ + lane * 4;
    float4 v = *(const float4*)p;
    float ss = v.x * v.x + v.y * v.y + v.z * v.z + v.w * v.w;
    #pragma unroll
    for (int off = 16; off; off >>= 1) ss += __shfl_xor_sync(0xffffffffu, ss, off);
    float r = rsqrtf(ss * (1.0f / HD_) + 1e-6f);
    float4 g = *(const float4*)&gamma[lane * 4];
    float hx = v.x * r * g.x, hy = v.y * r * g.y;
    float hz = v.z * r * g.z, hw = v.w * r * g.w;
    int ci = t * HD_ + lane * 4;
    float c0 = cosT[ci], s0 = sinT[ci], c1 = cosT[ci + 2], s1 = sinT[ci + 2];
    float ox = (hx * c0 - hy * s0) * outscale;
    float oy = (hy * c0 + hx * s0) * outscale;
    float oz = (hz * c1 - hw * s1) * outscale;
    float ow = (hw * c1 + hz * s1) * outscale;
    *(uint2*)&outh[(size_t)w * HD_ + lane * 4] = make_uint2(pack2(ox, oy), pack2(oz, ow));
}

// ---------------------------------------------------------------------------
// FP16 flash attention, cp.async double-buffered K/V.
// 128 q-rows/CTA, 8 warps, 64-wide K/V tiles, m16n8k16 QK^T and PV.
//   qs,ks: [row][hd] stride 136 halfs; vs: [hd][s] stride 72; ps: [row][s] 72.
// ---------------------------------------------------------------------------
#define AQ_ST 136
#define AV_ST 72
#define AP_ST 72
#define KBUF (64 * AQ_ST)
#define VBUF (128 * AV_ST)
#define ATTN_SMEM ((128*AQ_ST + 2*KBUF + 2*VBUF + 128*AP_ST) * 2)

__global__ __launch_bounds__(256, 1)
void attn_f16(const __half* __restrict__ qh, const __half* __restrict__ kh,
              const __half* __restrict__ vt, __half* __restrict__ oh)
{
    extern __shared__ __half hsm[];
    __half* qs = hsm;                       // 128 x 136
    __half* ks = qs + 128 * AQ_ST;          // 2 x (64 x 136)
    __half* vs = ks + 2 * KBUF;             // 2 x (128 x 72)
    __half* ps = vs + 2 * VBUF;             // 128 x 72

    int b = blockIdx.z, h = blockIdx.y;
    int kvh = h / G_;
    int t0 = blockIdx.x * 128;
    int tid = threadIdx.x, lane = tid & 31, warp = tid >> 5;
    int qr = lane >> 2;
    int ql = lane & 3;

    const __half* kbase = kh + ((size_t)(b * T_) * KV_ + kvh) * HD_;
    const __half* vbase = vt + ((size_t)(b * KV_ + kvh) * HD_) * T_;

    // Group 0: Q tile + K/V tile 0.
    #pragma unroll
    for (int p = 0; p < 8; p++) {
        int slot = p * 256 + tid;
        int row = slot >> 4, c8 = (slot & 15) << 3;
        cp16(smem_u32(&qs[row * AQ_ST + c8]),
             &qh[((size_t)(b * T_ + t0 + row) * H_ + h) * HD_ + c8]);
    }
    #pragma unroll
    for (int p = 0; p < 4; p++) {
        int slot = p * 256 + tid;
        int row = slot >> 4, c8 = (slot & 15) << 3;
        cp16(smem_u32(&ks[row * AQ_ST + c8]), &kbase[(size_t)row * (KV_ * HD_) + c8]);
    }
    #pragma unroll
    for (int p = 0; p < 4; p++) {
        int slot = p * 256 + tid;
        int hd = slot >> 3, s8 = (slot & 7) << 3;
        cp16(smem_u32(&vs[hd * AV_ST + s8]), &vbase[(size_t)hd * T_ + s8]);
    }
    CP_COMMIT();

    float m1 = -1e30f, m2 = -1e30f, l1 = 0.f, l2 = 0.f;
    float oa[16][4] = {};
    int r1 = warp * 16 + qr;

    const int NT = T_ / 64;
    for (int kt = 0; kt < NT; kt++) {
        int buf = kt & 1;
        if (kt + 1 < NT) {
            int nxt = buf ^ 1;
            int s0g = (kt + 1) * 64;
            #pragma unroll
            for (int p = 0; p < 4; p++) {
                int slot = p * 256 + tid;
                int row = slot >> 4, c8 = (slot & 15) << 3;
                cp16(smem_u32(&ks[nxt * KBUF + row * AQ_ST + c8]),
                     &kbase[(size_t)(s0g + row) * (KV_ * HD_) + c8]);
            }
            #pragma unroll
            for (int p = 0; p < 4; p++) {
                int slot = p * 256 + tid;
                int hd = slot >> 3, s8 = (slot & 7) << 3;
                cp16(smem_u32(&vs[nxt * VBUF + hd * AV_ST + s8]),
                     &vbase[(size_t)hd * T_ + s0g + s8]);
            }
        }
        CP_COMMIT();
        CP_WAIT1();
        __syncthreads();

        const __half* ksb = ks + buf * KBUF;
        const __half* vsb = vs + buf * VBUF;

        // S = Q @ K^T : 8 k16 steps over HD, 8 n-frags over 64 cols.
        float s[8][4] = {};
        #pragma unroll
        for (int k16 = 0; k16 < 128; k16 += 16) {
            int kc = k16 + ql * 2;
            uint32_t a0 = *(const uint32_t*)&qs[r1 * AQ_ST + kc];
            uint32_t a1 = *(const uint32_t*)&qs[(r1 + 8) * AQ_ST + kc];
            uint32_t a2 = *(const uint32_t*)&qs[r1 * AQ_ST + kc + 8];
            uint32_t a3 = *(const uint32_t*)&qs[(r1 + 8) * AQ_ST + kc + 8];
            #pragma unroll
            for (int nf = 0; nf < 8; nf++) {
                int n = nf * 8 + qr;
                uint32_t b0 = *(const uint32_t*)&ksb[n * AQ_ST + kc];
                uint32_t b1 = *(const uint32_t*)&ksb[n * AQ_ST + kc + 8];
                mma_f16(s[nf], a0, a1, a2, a3, b0, b1);
            }
        }

        // Online softmax (rows r1, r1+8).
        float rm1 = -1e30f, rm2 = -1e30f;
        #pragma unroll
        for (int nf = 0; nf < 8; nf++) {
            rm1 = fmaxf(rm1, fmaxf(s[nf][0], s[nf][1]));
            rm2 = fmaxf(rm2, fmaxf(s[nf][2], s[nf][3]));
        }
        #pragma unroll
        for (int off = 1; off <= 2; off <<= 1) {
            rm1 = fmaxf(rm1, __shfl_xor_sync(0xffffffffu, rm1, off));
            rm2 = fmaxf(rm2, __shfl_xor_sync(0xffffffffu, rm2, off));
        }
        float nm1 = fmaxf(m1, rm1), nm2 = fmaxf(m2, rm2);
        float rs1 = 0.f, rs2 = 0.f;
        #pragma unroll
        for (int nf = 0; nf < 8; nf++) {
            float p0 = __expf(s[nf][0] - nm1);
            float p1 = __expf(s[nf][1] - nm1);
            float p2 = __expf(s[nf][2] - nm2);
            float p3 = __expf(s[nf][3] - nm2);
            rs1 += p0 + p1; rs2 += p2 + p3;
            int c = nf * 8 + ql * 2;
            *(uint32_t*)&ps[r1 * AP_ST + c]       = pack2(p0, p1);
            *(uint32_t*)&ps[(r1 + 8) * AP_ST + c] = pack2(p2, p3);
        }
        #pragma unroll
        for (int off = 1; off <= 2; off <<= 1) {
            rs1 += __shfl_xor_sync(0xffffffffu, rs1, off);
            rs2 += __shfl_xor_sync(0xffffffffu, rs2, off);
        }
        float corr1 = __expf(m1 - nm1), corr2 = __expf(m2 - nm2);
        l1 = l1 * corr1 + rs1; m1 = nm1;
        l2 = l2 * corr2 + rs2; m2 = nm2;
        #pragma unroll
        for (int nf = 0; nf < 16; nf++) {
            oa[nf][0] *= corr1; oa[nf][1] *= corr1;
            oa[nf][2] *= corr2; oa[nf][3] *= corr2;
        }
        __syncwarp();  // P stripe is warp-private

        // O += P @ V : 4 k16 steps over s=64, 16 n-frags over hd=128.
        #pragma unroll
        for (int k16 = 0; k16 < 64; k16 += 16) {
            int kc = k16 + ql * 2;
            uint32_t a0 = *(const uint32_t*)&ps[r1 * AP_ST + kc];
            uint32_t a1 = *(const uint32_t*)&ps[(r1 + 8) * AP_ST + kc];
            uint32_t a2 = *(const uint32_t*)&ps[r1 * AP_ST + kc + 8];
            uint32_t a3 = *(const uint32_t*)&ps[(r1 + 8) * AP_ST + kc + 8];
            #pragma unroll
            for (int nf = 0; nf < 16; nf++) {
                int n = nf * 8 + qr;
                uint32_t b0 = *(const uint32_t*)&vsb[n * AV_ST + kc];
                uint32_t b1 = *(const uint32_t*)&vsb[n * AV_ST + kc + 8];
                mma_f16(oa[nf], a0, a1, a2, a3, b0, b1);
            }
        }
        __syncthreads();  // compute done before next iter's cp.async overwrites
    }

    float inv1 = 1.0f / l1, inv2 = 1.0f / l2;
    size_t base1 = ((size_t)(b * T_ + t0 + r1) * H_ + h) * HD_;
    size_t base2 = ((size_t)(b * T_ + t0 + r1 + 8) * H_ + h) * HD_;
    #pragma unroll
    for (int nf = 0; nf < 16; nf++) {
        int c = nf * 8 + ql * 2;
        *(uint32_t*)&oh[base1 + c] = pack2(oa[nf][0] * inv1, oa[nf][1] * inv1);
        *(uint32_t*)&oh[base2 + c] = pack2(oa[nf][2] * inv2, oa[nf][3] * inv2);
    }
}

// ---------------------------------------------------------------------------
// Launch
// ---------------------------------------------------------------------------
extern "C" void kernel_launch(void* const* d_in, const int* in_sizes, int n_in,
                              void* d_out, int out_size)
{
    const float* x    = (const float*)d_in[0];
    const float* cosT = (const float*)d_in[1];
    const float* sinT = (const float*)d_in[2];
    const float* Wq   = (const float*)d_in[3];
    const float* Wk   = (const float*)d_in[4];
    const float* Wv   = (const float*)d_in[5];
    const float* Wo   = (const float*)d_in[6];
    const float* qg   = (const float*)d_in[7];
    const float* kg   = (const float*)d_in[8];

    float *q, *k, *v;
    __half *xh, *qh, *kh, *vt, *oh, *wt;
    cudaGetSymbolAddress((void**)&q,  g_q);
    cudaGetSymbolAddress((void**)&k,  g_k);
    cudaGetSymbolAddress((void**)&v,  g_v);
    cudaGetSymbolAddress((void**)&xh, g_xh);
    cudaGetSymbolAddress((void**)&qh, g_qh);
    cudaGetSymbolAddress((void**)&kh, g_kh);
    cudaGetSymbolAddress((void**)&vt, g_vt);
    cudaGetSymbolAddress((void**)&oh, g_oh);
    cudaGetSymbolAddress((void**)&wt, g_wt);

    __half* WqkvT = wt;                      // [4096][2048]
    __half* WoT   = wt + 8 * 1024 * 1024;    // [2048][2048]

    const int M = B_ * T_;  // 8192

    // Weight prep: WqT rows [0,2048), WkT [2048,3072), WvT [3072,4096).
    transpose_cvt<<<dim3(2048/32, 2048/32), 256>>>(Wq, WqkvT, DM_, 2048);
    transpose_cvt<<<dim3(1024/32, 2048/32), 256>>>(Wk, WqkvT + 2048ull*2048, DM_, 1024);
    transpose_cvt<<<dim3(1024/32, 2048/32), 256>>>(Wv, WqkvT + 3072ull*2048, DM_, 1024);
    transpose_cvt<<<dim3(2048/32, 2048/32), 256>>>(Wo, WoT, H_*HD_, 2048);
    cvt_half<<<(M * DM_) / (256 * 8), 256>>>(x, xh);

    cudaFuncSetAttribute(gemm_f16h, cudaFuncAttributeMaxDynamicSharedMemorySize, GEMM_SMEM);
    // Fused QKV GEMM: N = 4096.
    gemm_f16h<<<dim3(4096/128, M/128), 256, GEMM_SMEM>>>(xh, WqkvT, q, k, v, M, 4096, DM_);

    rmsrope_h<<<(M * H_) / 8, 256>>>(q, qh, qg, cosT, sinT, H_, 0.0883883476483184405f);
    rmsrope_h<<<(M * KV_) / 8, 256>>>(k, kh, kg, cosT, sinT, KV_, 1.0f);
    vtrans<<<dim3(T_/32, HD_/32, B_*KV_), 256>>>(v, vt);

    cudaFuncSetAttribute(attn_f16, cudaFuncAttributeMaxDynamicSharedMemorySize, ATTN_SMEM);
    attn_f16<<<dim3(T_ / 128, H_, B_), 256, ATTN_SMEM>>>(qh, kh, vt, oh);

    gemm_f16h<<<dim3(DM_/128, M/128), 256, GEMM_SMEM>>>(oh, WoT, (float*)d_out, nullptr, nullptr,
                                                        M, DM_, DM_);
}

// round 8
// speedup vs baseline: 2.2776x; 1.0366x over previous
#include <cuda_runtime.h>
#include <cuda_fp16.h>
#include <math.h>
#include <stdint.h>

#define B_ 4
#define T_ 2048
#define DM_ 2048
#define H_ 16
#define KV_ 8
#define HD_ 128
#define G_ 2

// Scratch (no allocations allowed) — static device globals.
__device__ float  g_q[B_*T_*H_*HD_];    // fp32 QKV GEMM out
__device__ float  g_k[B_*T_*KV_*HD_];
__device__ float  g_v[B_*T_*KV_*HD_];
__device__ __half g_xh[B_*T_*DM_];
__device__ __half g_qh[B_*T_*H_*HD_];
__device__ __half g_kh[B_*T_*KV_*HD_];
__device__ __half g_vt[B_*KV_*HD_*T_];  // V transposed [b][kv][hd][t]
__device__ __half g_oh[B_*T_*H_*HD_];
__device__ __half g_wt[12*1024*1024];   // WqkvT [4096][2048], WoT [2048][2048]

// ---------------------------------------------------------------------------
// Helpers
// ---------------------------------------------------------------------------
__device__ __forceinline__ uint32_t h2u(__half2 h) { return *(uint32_t*)&h; }
__device__ __forceinline__ uint32_t pack2(float lo, float hi) {
    return h2u(__floats2half2_rn(lo, hi));
}

__device__ __forceinline__ void mma_f16(float c[4],
                                        uint32_t a0, uint32_t a1, uint32_t a2, uint32_t a3,
                                        uint32_t b0, uint32_t b1) {
    asm volatile(
        "mma.sync.aligned.m16n8k16.row.col.f32.f16.f16.f32 "
        "{%0,%1,%2,%3}, {%4,%5,%6,%7}, {%8,%9}, {%0,%1,%2,%3};"
        : "+f"(c[0]), "+f"(c[1]), "+f"(c[2]), "+f"(c[3])
        : "r"(a0), "r"(a1), "r"(a2), "r"(a3), "r"(b0), "r"(b1));
}

__device__ __forceinline__ uint32_t smem_u32(const void* p) {
    uint32_t a;
    asm("{ .reg .u64 t; cvta.to.shared.u64 t, %1; cvt.u32.u64 %0, t; }" : "=r"(a) : "l"(p));
    return a;
}
__device__ __forceinline__ void cp16(uint32_t s, const void* g) {
    asm volatile("cp.async.ca.shared.global [%0], [%1], 16;" :: "r"(s), "l"(g));
}
#define CP_COMMIT() asm volatile("cp.async.commit_group;")
#define CP_WAIT1()  asm volatile("cp.async.wait_group 1;")

// ---------------------------------------------------------------------------
// Weight transpose + fp16 convert: W[K][N] -> WT[N][K] (half).
// ---------------------------------------------------------------------------
__global__ void transpose_cvt(const float* __restrict__ W, __half* __restrict__ WT,
                              int K, int N)
{
    __shared__ float t[32][33];
    int n0 = blockIdx.x * 32, k0 = blockIdx.y * 32;
    int tx = threadIdx.x & 31, ty = threadIdx.x >> 5;
    #pragma unroll
    for (int j = 0; j < 4; j++)
        t[ty + 8 * j][tx] = W[(size_t)(k0 + ty + 8 * j) * N + n0 + tx];
    __syncthreads();
    #pragma unroll
    for (int j = 0; j < 4; j++)
        WT[(size_t)(n0 + ty + 8 * j) * K + k0 + tx] = __float2half_rn(t[tx][ty + 8 * j]);
}

// fp32 -> fp16 bulk convert (8 elements/thread).
__global__ void cvt_half(const float* __restrict__ in, __half* __restrict__ out)
{
    size_t i = ((size_t)blockIdx.x * blockDim.x + threadIdx.x) * 8;
    float4 a = *(const float4*)&in[i];
    float4 b = *(const float4*)&in[i + 4];
    *(uint4*)&out[i] = make_uint4(pack2(a.x, a.y), pack2(a.z, a.w),
                                  pack2(b.x, b.y), pack2(b.z, b.w));
}

// V transpose: v[b][t][kv][hd] fp32 -> vt[b][kv][hd][t] fp16.
__global__ void vtrans(const float* __restrict__ v, __half* __restrict__ vt)
{
    __shared__ float t[32][33];
    int t0 = blockIdx.x * 32, d0 = blockIdx.y * 32;
    int bk = blockIdx.z;
    int b = bk >> 3, kvh = bk & 7;
    int tx = threadIdx.x & 31, ty = threadIdx.x >> 5;
    #pragma unroll
    for (int j = 0; j < 4; j++)
        t[ty + 8 * j][tx] = v[(((size_t)(b * T_ + t0 + ty + 8 * j) * KV_ + kvh) << 7) + d0 + tx];
    __syncthreads();
    #pragma unroll
    for (int j = 0; j < 4; j++)
        vt[((size_t)bk * HD_ + d0 + ty + 8 * j) * T_ + t0 + tx] = __float2half_rn(t[tx][ty + 8 * j]);
}

// ---------------------------------------------------------------------------
// All-fp16 pipelined GEMM: C[M,N] = A[M,K] * WT[N,K]^T, C fp32.
// Block 128x256, BK=64, cp.async 2-stage, 8 warps (2m x 4n of 64x64 tiles).
// Smem row stride 72 halfs (36 words ≡ 4 mod 32): conflict-free u32 frags.
// ---------------------------------------------------------------------------
#define GST 72
#define GT_A (128 * GST)
#define GT_B (256 * GST)
#define GEMM_SMEM ((2 * (GT_A + GT_B)) * 2)   // 110592 bytes

__global__ __launch_bounds__(256, 1)
void gemm_f16h(const __half* __restrict__ A, const __half* __restrict__ WT,
               float* __restrict__ Cq, float* __restrict__ Ck, float* __restrict__ Cv,
               int M, int N, int K)
{
    extern __shared__ __half gsm[];
    __half* As[2] = { gsm, gsm + GT_A };
    __half* Bs[2] = { gsm + 2 * GT_A, gsm + 2 * GT_A + GT_B };

    int tid  = threadIdx.x;
    int lane = tid & 31;
    int warp = tid >> 5;
    int qr = lane >> 2, ql = lane & 3;
    int wm = (warp & 1) * 64;
    int wn = (warp >> 1) * 64;
    int bm = blockIdx.y * 128, bn = blockIdx.x * 256;

    float acc[4][8][4] = {};   // [fm][fn][reg], warp tile 64x64
    const int NT = K / 64;

    // Prefetch tile 0: A 4 cp16/thread, B 8 cp16/thread.
    #pragma unroll
    for (int p = 0; p < 4; p++) {
        int slot = p * 256 + tid;
        int r = slot >> 3, c8 = (slot & 7) << 3;
        cp16(smem_u32(&As[0][r * GST + c8]), &A[(size_t)(bm + r) * K + c8]);
    }
    #pragma unroll
    for (int p = 0; p < 8; p++) {
        int slot = p * 256 + tid;
        int r = slot >> 3, c8 = (slot & 7) << 3;
        cp16(smem_u32(&Bs[0][r * GST + c8]), &WT[(size_t)(bn + r) * K + c8]);
    }
    CP_COMMIT();

    for (int kt = 0; kt < NT; kt++) {
        int buf = kt & 1;
        if (kt + 1 < NT) {
            int nxt = buf ^ 1;
            int k0 = (kt + 1) * 64;
            #pragma unroll
            for (int p = 0; p < 4; p++) {
                int slot = p * 256 + tid;
                int r = slot >> 3, c8 = (slot & 7) << 3;
                cp16(smem_u32(&As[nxt][r * GST + c8]), &A[(size_t)(bm + r) * K + k0 + c8]);
            }
            #pragma unroll
            for (int p = 0; p < 8; p++) {
                int slot = p * 256 + tid;
                int r = slot >> 3, c8 = (slot & 7) << 3;
                cp16(smem_u32(&Bs[nxt][r * GST + c8]), &WT[(size_t)(bn + r) * K + k0 + c8]);
            }
        }
        CP_COMMIT();
        CP_WAIT1();
        __syncthreads();

        const __half* a_sm = As[buf];
        const __half* b_sm = Bs[buf];
        #pragma unroll
        for (int ks = 0; ks < 4; ks++) {
            int kc = ks * 16 + ql * 2;
            uint32_t af[4][4];
            #pragma unroll
            for (int fm = 0; fm < 4; fm++) {
                int r = wm + fm * 16 + qr;
                af[fm][0] = *(const uint32_t*)&a_sm[r * GST + kc];
                af[fm][1] = *(const uint32_t*)&a_sm[(r + 8) * GST + kc];
                af[fm][2] = *(const uint32_t*)&a_sm[r * GST + kc + 8];
                af[fm][3] = *(const uint32_t*)&a_sm[(r + 8) * GST + kc + 8];
            }
            #pragma unroll
            for (int fn = 0; fn < 8; fn++) {
                int n = wn + fn * 8 + qr;
                uint32_t b0 = *(const uint32_t*)&b_sm[n * GST + kc];
                uint32_t b1 = *(const uint32_t*)&b_sm[n * GST + kc + 8];
                #pragma unroll
                for (int fm = 0; fm < 4; fm++)
                    mma_f16(acc[fm][fn], af[fm][0], af[fm][1], af[fm][2], af[fm][3], b0, b1);
            }
        }
        __syncthreads();
    }

    // Epilogue routing (fused QKV when Ck != null; bn blocks are 256-wide).
    float* Cb; int ldc, cofs;
    if (Ck == nullptr)      { Cb = Cq; ldc = N;    cofs = bn; }
    else if (bn < 2048)     { Cb = Cq; ldc = 2048; cofs = bn; }
    else if (bn < 3072)     { Cb = Ck; ldc = 1024; cofs = bn - 2048; }
    else                    { Cb = Cv; ldc = 1024; cofs = bn - 3072; }

    #pragma unroll
    for (int fm = 0; fm < 4; fm++) {
        #pragma unroll
        for (int fn = 0; fn < 8; fn++) {
            int r = bm + wm + fm * 16 + qr;
            int c = cofs + wn + fn * 8 + ql * 2;
            *(float2*)&Cb[(size_t)r * ldc + c]       = make_float2(acc[fm][fn][0], acc[fm][fn][1]);
            *(float2*)&Cb[(size_t)(r + 8) * ldc + c] = make_float2(acc[fm][fn][2], acc[fm][fn][3]);
        }
    }
}

// ---------------------------------------------------------------------------
// Fused RMSNorm + interleaved RoPE; fp32 in, fp16 out (1/sqrt(HD) folded into q).
// ---------------------------------------------------------------------------
__global__ void rmsrope_h(const float* __restrict__ in, __half* __restrict__ outh,
                          const float* __restrict__ gamma,
                          const float* __restrict__ cosT, const float* __restrict__ sinT,
                          int nheads, float outscale)
{
    int gid  = blockIdx.x * blockDim.x + threadIdx.x;
    int lane = gid & 31;
    int w    = gid >> 5;
    int t    = (w / nheads) % T_;
    const float* p = in + (size_t)w * HD_ + lane * 4;
    float4 v = *(const float4*)p;
    float ss = v.x * v.x + v.y * v.y + v.z * v.z + v.w * v.w;
    #pragma unroll
    for (int off = 16; off; off >>= 1) ss += __shfl_xor_sync(0xffffffffu, ss, off);
    float r = rsqrtf(ss * (1.0f / HD_) + 1e-6f);
    float4 g = *(const float4*)&gamma[lane * 4];
    float hx = v.x * r * g.x, hy = v.y * r * g.y;
    float hz = v.z * r * g.z, hw = v.w * r * g.w;
    int ci = t * HD_ + lane * 4;
    float c0 = cosT[ci], s0 = sinT[ci], c1 = cosT[ci + 2], s1 = sinT[ci + 2];
    float ox = (hx * c0 - hy * s0) * outscale;
    float oy = (hy * c0 + hx * s0) * outscale;
    float oz = (hz * c1 - hw * s1) * outscale;
    float ow = (hw * c1 + hz * s1) * outscale;
    *(uint2*)&outh[(size_t)w * HD_ + lane * 4] = make_uint2(pack2(ox, oy), pack2(oz, ow));
}

// ---------------------------------------------------------------------------
// FP16 flash attention, 256 q-rows/CTA, 8 warps (32 rows each: 2 m16 frags),
// 64-wide K/V tiles double-buffered via cp.async, m16n8k16 QK^T and PV.
//   qs,ks: [row][hd] stride 136 halfs; vs: [hd][s] stride 72; ps: [row][s] 72.
// ---------------------------------------------------------------------------
#define AQ_ST 136
#define AV_ST 72
#define AP_ST 72
#define KBUF (64 * AQ_ST)
#define VBUF (128 * AV_ST)
#define ATTN_SMEM ((256*AQ_ST + 2*KBUF + 2*VBUF + 256*AP_ST) * 2)   // 178176 B

__global__ __launch_bounds__(256, 1)
void attn_f16(const __half* __restrict__ qh, const __half* __restrict__ kh,
              const __half* __restrict__ vt, __half* __restrict__ oh)
{
    extern __shared__ __half hsm[];
    __half* qs = hsm;                       // 256 x 136
    __half* ks = qs + 256 * AQ_ST;          // 2 x (64 x 136)
    __half* vs = ks + 2 * KBUF;             // 2 x (128 x 72)
    __half* ps = vs + 2 * VBUF;             // 256 x 72

    int b = blockIdx.z, h = blockIdx.y;
    int kvh = h / G_;
    int t0 = blockIdx.x * 256;
    int tid = threadIdx.x, lane = tid & 31, warp = tid >> 5;
    int qr = lane >> 2;
    int ql = lane & 3;

    const __half* kbase = kh + ((size_t)(b * T_) * KV_ + kvh) * HD_;
    const __half* vbase = vt + ((size_t)(b * KV_ + kvh) * HD_) * T_;

    // Stage Q (256x128) + K/V tile 0.
    #pragma unroll
    for (int p = 0; p < 16; p++) {
        int slot = p * 256 + tid;
        int row = slot >> 4, c8 = (slot & 15) << 3;
        cp16(smem_u32(&qs[row * AQ_ST + c8]),
             &qh[((size_t)(b * T_ + t0 + row) * H_ + h) * HD_ + c8]);
    }
    #pragma unroll
    for (int p = 0; p < 4; p++) {
        int slot = p * 256 + tid;
        int row = slot >> 4, c8 = (slot & 15) << 3;
        cp16(smem_u32(&ks[row * AQ_ST + c8]), &kbase[(size_t)row * (KV_ * HD_) + c8]);
    }
    #pragma unroll
    for (int p = 0; p < 4; p++) {
        int slot = p * 256 + tid;
        int hd = slot >> 3, s8 = (slot & 7) << 3;
        cp16(smem_u32(&vs[hd * AV_ST + s8]), &vbase[(size_t)hd * T_ + s8]);
    }
    CP_COMMIT();

    // Softmax state per row-frag f (rows r1+16f and r1+16f+8).
    float m[2][2] = {{-1e30f, -1e30f}, {-1e30f, -1e30f}};
    float l[2][2] = {};
    float oa[2][16][4] = {};
    int r1 = warp * 32 + qr;

    const int NT = T_ / 64;
    for (int kt = 0; kt < NT; kt++) {
        int buf = kt & 1;
        if (kt + 1 < NT) {
            int nxt = buf ^ 1;
            int s0g = (kt + 1) * 64;
            #pragma unroll
            for (int p = 0; p < 4; p++) {
                int slot = p * 256 + tid;
                int row = slot >> 4, c8 = (slot & 15) << 3;
                cp16(smem_u32(&ks[nxt * KBUF + row * AQ_ST + c8]),
                     &kbase[(size_t)(s0g + row) * (KV_ * HD_) + c8]);
            }
            #pragma unroll
            for (int p = 0; p < 4; p++) {
                int slot = p * 256 + tid;
                int hd = slot >> 3, s8 = (slot & 7) << 3;
                cp16(smem_u32(&vs[nxt * VBUF + hd * AV_ST + s8]),
                     &vbase[(size_t)hd * T_ + s0g + s8]);
            }
        }
        CP_COMMIT();
        CP_WAIT1();
        __syncthreads();

        const __half* ksb = ks + buf * KBUF;
        const __half* vsb = vs + buf * VBUF;

        // S = Q @ K^T : 8 k16 steps over HD, 8 n-frags, 2 row-frags.
        float s[2][8][4] = {};
        #pragma unroll
        for (int k16 = 0; k16 < 128; k16 += 16) {
            int kc = k16 + ql * 2;
            uint32_t af[2][4];
            #pragma unroll
            for (int f = 0; f < 2; f++) {
                int r = r1 + f * 16;
                af[f][0] = *(const uint32_t*)&qs[r * AQ_ST + kc];
                af[f][1] = *(const uint32_t*)&qs[(r + 8) * AQ_ST + kc];
                af[f][2] = *(const uint32_t*)&qs[r * AQ_ST + kc + 8];
                af[f][3] = *(const uint32_t*)&qs[(r + 8) * AQ_ST + kc + 8];
            }
            #pragma unroll
            for (int nf = 0; nf < 8; nf++) {
                int n = nf * 8 + qr;
                uint32_t b0 = *(const uint32_t*)&ksb[n * AQ_ST + kc];
                uint32_t b1 = *(const uint32_t*)&ksb[n * AQ_ST + kc + 8];
                #pragma unroll
                for (int f = 0; f < 2; f++)
                    mma_f16(s[f][nf], af[f][0], af[f][1], af[f][2], af[f][3], b0, b1);
            }
        }

        // Online softmax per row-frag.
        #pragma unroll
        for (int f = 0; f < 2; f++) {
            float rm1 = -1e30f, rm2 = -1e30f;
            #pragma unroll
            for (int nf = 0; nf < 8; nf++) {
                rm1 = fmaxf(rm1, fmaxf(s[f][nf][0], s[f][nf][1]));
                rm2 = fmaxf(rm2, fmaxf(s[f][nf][2], s[f][nf][3]));
            }
            #pragma unroll
            for (int off = 1; off <= 2; off <<= 1) {
                rm1 = fmaxf(rm1, __shfl_xor_sync(0xffffffffu, rm1, off));
                rm2 = fmaxf(rm2, __shfl_xor_sync(0xffffffffu, rm2, off));
            }
            float nm1 = fmaxf(m[f][0], rm1), nm2 = fmaxf(m[f][1], rm2);
            float rs1 = 0.f, rs2 = 0.f;
            int rr = r1 + f * 16;
            #pragma unroll
            for (int nf = 0; nf < 8; nf++) {
                float p0 = __expf(s[f][nf][0] - nm1);
                float p1 = __expf(s[f][nf][1] - nm1);
                float p2 = __expf(s[f][nf][2] - nm2);
                float p3 = __expf(s[f][nf][3] - nm2);
                rs1 += p0 + p1; rs2 += p2 + p3;
                int c = nf * 8 + ql * 2;
                *(uint32_t*)&ps[rr * AP_ST + c]       = pack2(p0, p1);
                *(uint32_t*)&ps[(rr + 8) * AP_ST + c] = pack2(p2, p3);
            }
            #pragma unroll
            for (int off = 1; off <= 2; off <<= 1) {
                rs1 += __shfl_xor_sync(0xffffffffu, rs1, off);
                rs2 += __shfl_xor_sync(0xffffffffu, rs2, off);
            }
            float corr1 = __expf(m[f][0] - nm1), corr2 = __expf(m[f][1] - nm2);
            l[f][0] = l[f][0] * corr1 + rs1; m[f][0] = nm1;
            l[f][1] = l[f][1] * corr2 + rs2; m[f][1] = nm2;
            #pragma unroll
            for (int nf = 0; nf < 16; nf++) {
                oa[f][nf][0] *= corr1; oa[f][nf][1] *= corr1;
                oa[f][nf][2] *= corr2; oa[f][nf][3] *= corr2;
            }
        }
        __syncwarp();  // P stripe is warp-private

        // O += P @ V : 4 k16 steps over s=64, 16 n-frags over hd=128.
        #pragma unroll
        for (int k16 = 0; k16 < 64; k16 += 16) {
            int kc = k16 + ql * 2;
            uint32_t af[2][4];
            #pragma unroll
            for (int f = 0; f < 2; f++) {
                int rr = r1 + f * 16;
                af[f][0] = *(const uint32_t*)&ps[rr * AP_ST + kc];
                af[f][1] = *(const uint32_t*)&ps[(rr + 8) * AP_ST + kc];
                af[f][2] = *(const uint32_t*)&ps[rr * AP_ST + kc + 8];
                af[f][3] = *(const uint32_t*)&ps[(rr + 8) * AP_ST + kc + 8];
            }
            #pragma unroll
            for (int nf = 0; nf < 16; nf++) {
                int n = nf * 8 + qr;
                uint32_t b0 = *(const uint32_t*)&vsb[n * AV_ST + kc];
                uint32_t b1 = *(const uint32_t*)&vsb[n * AV_ST + kc + 8];
                #pragma unroll
                for (int f = 0; f < 2; f++)
                    mma_f16(oa[f][nf], af[f][0], af[f][1], af[f][2], af[f][3], b0, b1);
            }
        }
        __syncthreads();  // compute done before next iter's cp.async overwrites
    }

    #pragma unroll
    for (int f = 0; f < 2; f++) {
        float inv1 = 1.0f / l[f][0], inv2 = 1.0f / l[f][1];
        int rr = r1 + f * 16;
        size_t base1 = ((size_t)(b * T_ + t0 + rr) * H_ + h) * HD_;
        size_t base2 = ((size_t)(b * T_ + t0 + rr + 8) * H_ + h) * HD_;
        #pragma unroll
        for (int nf = 0; nf < 16; nf++) {
            int c = nf * 8 + ql * 2;
            *(uint32_t*)&oh[base1 + c] = pack2(oa[f][nf][0] * inv1, oa[f][nf][1] * inv1);
            *(uint32_t*)&oh[base2 + c] = pack2(oa[f][nf][2] * inv2, oa[f][nf][3] * inv2);
        }
    }
}

// ---------------------------------------------------------------------------
// Launch
// ---------------------------------------------------------------------------
extern "C" void kernel_launch(void* const* d_in, const int* in_sizes, int n_in,
                              void* d_out, int out_size)
{
    const float* x    = (const float*)d_in[0];
    const float* cosT = (const float*)d_in[1];
    const float* sinT = (const float*)d_in[2];
    const float* Wq   = (const float*)d_in[3];
    const float* Wk   = (const float*)d_in[4];
    const float* Wv   = (const float*)d_in[5];
    const float* Wo   = (const float*)d_in[6];
    const float* qg   = (const float*)d_in[7];
    const float* kg   = (const float*)d_in[8];

    float *q, *k, *v;
    __half *xh, *qh, *kh, *vt, *oh, *wt;
    cudaGetSymbolAddress((void**)&q,  g_q);
    cudaGetSymbolAddress((void**)&k,  g_k);
    cudaGetSymbolAddress((void**)&v,  g_v);
    cudaGetSymbolAddress((void**)&xh, g_xh);
    cudaGetSymbolAddress((void**)&qh, g_qh);
    cudaGetSymbolAddress((void**)&kh, g_kh);
    cudaGetSymbolAddress((void**)&vt, g_vt);
    cudaGetSymbolAddress((void**)&oh, g_oh);
    cudaGetSymbolAddress((void**)&wt, g_wt);

    __half* WqkvT = wt;                      // [4096][2048]
    __half* WoT   = wt + 8 * 1024 * 1024;    // [2048][2048]

    const int M = B_ * T_;  // 8192

    transpose_cvt<<<dim3(2048/32, 2048/32), 256>>>(Wq, WqkvT, DM_, 2048);
    transpose_cvt<<<dim3(1024/32, 2048/32), 256>>>(Wk, WqkvT + 2048ull*2048, DM_, 1024);
    transpose_cvt<<<dim3(1024/32, 2048/32), 256>>>(Wv, WqkvT + 3072ull*2048, DM_, 1024);
    transpose_cvt<<<dim3(2048/32, 2048/32), 256>>>(Wo, WoT, H_*HD_, 2048);
    cvt_half<<<(M * DM_) / (256 * 8), 256>>>(x, xh);

    cudaFuncSetAttribute(gemm_f16h, cudaFuncAttributeMaxDynamicSharedMemorySize, GEMM_SMEM);
    gemm_f16h<<<dim3(4096/256, M/128), 256, GEMM_SMEM>>>(xh, WqkvT, q, k, v, M, 4096, DM_);

    rmsrope_h<<<(M * H_) / 8, 256>>>(q, qh, qg, cosT, sinT, H_, 0.0883883476483184405f);
    rmsrope_h<<<(M * KV_) / 8, 256>>>(k, kh, kg, cosT, sinT, KV_, 1.0f);
    vtrans<<<dim3(T_/32, HD_/32, B_*KV_), 256>>>(v, vt);

    cudaFuncSetAttribute(attn_f16, cudaFuncAttributeMaxDynamicSharedMemorySize, ATTN_SMEM);
    attn_f16<<<dim3(T_ / 256, H_, B_), 256, ATTN_SMEM>>>(qh, kh, vt, oh);

    gemm_f16h<<<dim3(DM_/256, M/128), 256, GEMM_SMEM>>>(oh, WoT, (float*)d_out, nullptr, nullptr,
                                                        M, DM_, DM_);
}